// round 8
// baseline (speedup 1.0000x reference)
#include <cuda_runtime.h>
#include <cuda_bf16.h>

#define NN   50000
#define DD   128
#define EE   400000
#define NMOL 256
#define OUTC 32

typedef unsigned long long u64;

// ---------------- device scratch (no allocations allowed) ----------------
__device__ float g_s1[NN * DD];
__device__ float g_s2[NN * DD];
__device__ float g_Abuf[NN * DD];
__device__ float g_mol[NMOL * DD];
__device__ int   g_is64;

// ---------------- f32x2 helpers ----------------
__device__ __forceinline__ void fma2(u64 &d, u64 a, u64 b) {
    asm("fma.rn.f32x2 %0, %1, %2, %0;" : "+l"(d) : "l"(a), "l"(b));
}
__device__ __forceinline__ float sum2(u64 v) {
    float lo, hi;
    asm("mov.b64 {%0,%1}, %2;" : "=f"(lo), "=f"(hi) : "l"(v));
    return lo + hi;
}

// ---------------- index width detection (int32 vs int64) ----------------
__global__ void detect_kernel(const int* p) {
    if (threadIdx.x == 0) {
        int all0 = 1;
        for (int i = 0; i < 64; i++)
            if (p[2 * i + 1] != 0) { all0 = 0; break; }
        g_is64 = all0;  // int64 little-endian: high words all zero (values < N)
    }
}
__device__ __forceinline__ int load_idx(const void* p, int i) {
    if (g_is64) return (int)((const long long*)p)[i];
    return ((const int*)p)[i];
}

// ---------------- zero fill (vectorized) ----------------
__global__ void zero_kernel(float4* p, int n4) {
    int i = blockIdx.x * blockDim.x + threadIdx.x;
    int stride = gridDim.x * blockDim.x;
    float4 z = make_float4(0.f, 0.f, 0.f, 0.f);
    for (; i < n4; i += stride) p[i] = z;
}

// ================= precompute: A = S @ [Win_top | Win_bot]  ([N,128]x[128,128]) ======
#define PC_STRIDE 132
#define PC_SMEM_BYTES ((128 * PC_STRIDE + 64 * PC_STRIDE) * 4)

__global__ __launch_bounds__(256, 2)
void precompute_kernel(const float* __restrict__ s, float* __restrict__ out,
                       const float* __restrict__ Win_t) {
    extern __shared__ float sm[];
    float* wT = sm;                        // [128 j][132]
    float* ss = sm + 128 * PC_STRIDE;      // [64 a][132]
    int tid = threadIdx.x;
    int abase = blockIdx.x * 64;

    for (int i = tid; i < 128 * 128; i += 256) {
        int k = i >> 7, j = i & 127;
        float v = (j < 64) ? Win_t[k * 64 + j] : Win_t[(128 + k) * 64 + (j - 64)];
        wT[j * PC_STRIDE + k] = v;
    }
    for (int i = tid; i < 64 * 32; i += 256) {
        int a = i >> 5, kq = (i & 31) * 4;
        int atom = abase + a;
        float4 v = (atom < NN) ? *(const float4*)&s[(size_t)atom * DD + kq]
                               : make_float4(0.f, 0.f, 0.f, 0.f);
        *(float4*)&ss[a * PC_STRIDE + kq] = v;
    }
    __syncthreads();

    int jg = tid & 31;
    int a0 = (tid >> 5) * 8;
    u64 acc[8][4];
#pragma unroll
    for (int i = 0; i < 8; i++)
#pragma unroll
        for (int c = 0; c < 4; c++) acc[i][c] = 0ull;

#pragma unroll 2
    for (int k = 0; k < 128; k += 4) {
        ulonglong2 wp[4];
#pragma unroll
        for (int c = 0; c < 4; c++)
            wp[c] = *(const ulonglong2*)&wT[(jg + 32 * c) * PC_STRIDE + k];
#pragma unroll
        for (int h = 0; h < 2; h++) {
#pragma unroll
            for (int i = 0; i < 4; i++) {
                int r = h * 4 + i;
                ulonglong2 hv = *(const ulonglong2*)&ss[(a0 + r) * PC_STRIDE + k];
#pragma unroll
                for (int c = 0; c < 4; c++) {
                    fma2(acc[r][c], hv.x, wp[c].x);
                    fma2(acc[r][c], hv.y, wp[c].y);
                }
            }
        }
    }

#pragma unroll
    for (int i = 0; i < 8; i++) {
        int atom = abase + a0 + i;
        if (atom < NN) {
#pragma unroll
            for (int c = 0; c < 4; c++)
                out[(size_t)atom * DD + jg + 32 * c] = sum2(acc[i][c]);
        }
    }
}

// ================= edge kernel: 128 edges per block, 512 threads ======================
// Warp w (of 16): edge group (w>>1)*16 (16 edges), j-half (w&1).
// GEMM1: 1 j per lane (j-half of 64), 16 edges -> weight load amortized 16x.
// GEMM2: 2 j per lane (j-half of 128), 16 edges.
#define WSTRIDE 68
#define HSTRIDE 68
#define ES_WHT 0
#define ES_WOT (ES_WHT + 64 * WSTRIDE)     // 4352
#define ES_H   (ES_WOT + 128 * WSTRIDE)    // 13056
#define ES_BH  (ES_H + 128 * HSTRIDE)      // 21760
#define ES_BO  (ES_BH + 64)                // 21824
#define ES_BI  (ES_BO + 128)               // 21952
#define ES_IDX (ES_BI + 64)                // 22016
#define ES_TOT (ES_IDX + 256)              // 22272
#define EDGE_SMEM_BYTES (ES_TOT * 4)

__global__ __launch_bounds__(512, 1)
void edge_kernel(const float* __restrict__ A, float* __restrict__ sn,
                 const void* __restrict__ srcp, const void* __restrict__ dstp,
                 const float* __restrict__ Wh_t, const float* __restrict__ bh_t,
                 const float* __restrict__ Wo_t, const float* __restrict__ bo_t,
                 const float* __restrict__ bi_t) {
    extern __shared__ float sm[];
    float* whT = sm + ES_WHT;   // [64 j][68]
    float* woT = sm + ES_WOT;   // [128 j][68]
    float* hb  = sm + ES_H;     // [128 e][68]  (h0, then h1)
    float* bh  = sm + ES_BH;
    float* bo  = sm + ES_BO;
    float* bi  = sm + ES_BI;
    int*   dsts = (int*)(sm + ES_IDX);
    int*   srcs = dsts + 128;
    int tid = threadIdx.x;
    int eb = blockIdx.x * 128;

    for (int i = tid; i < 64 * 64; i += 512) {
        int k = i >> 6, j = i & 63;
        whT[j * WSTRIDE + k] = Wh_t[i];
    }
    for (int i = tid; i < 64 * 128; i += 512) {
        int k = i >> 7, j = i & 127;
        woT[j * WSTRIDE + k] = Wo_t[i];
    }
    if (tid < 128) {
        dsts[tid] = load_idx(dstp, eb + tid);
        srcs[tid] = load_idx(srcp, eb + tid);
        if (tid < 64) { bh[tid] = bh_t[tid]; bi[tid] = bi_t[tid]; }
        else           bo[tid - 64] = bo_t[tid - 64];
    } else if (tid < 192) {
        bo[tid - 128 + 64] = bo_t[tid - 128 + 64];
    }
    __syncthreads();

    // layer 0: hb[e][j] = relu(A[dst][j] + A[src][64+j] + b_in[j]),  j<64
    {
        int e = tid >> 2;               // 0..127
        int j0 = (tid & 3) * 16;
        const float* ad = A + (size_t)dsts[e] * DD;
        const float* as = A + (size_t)srcs[e] * DD + 64;
#pragma unroll
        for (int v = 0; v < 16; v += 4) {
            int j = j0 + v;
            float4 x = *(const float4*)(ad + j);
            float4 y = *(const float4*)(as + j);
            float4 b = *(const float4*)(bi + j);
            float4 r;
            r.x = fmaxf(x.x + y.x + b.x, 0.f);
            r.y = fmaxf(x.y + y.y + b.y, 0.f);
            r.z = fmaxf(x.z + y.z + b.z, 0.f);
            r.w = fmaxf(x.w + y.w + b.w, 0.f);
            *(float4*)&hb[e * HSTRIDE + j] = r;
        }
    }
    __syncthreads();

    int w    = tid >> 5;
    int lane = tid & 31;
    int e0   = (w >> 1) * 16;           // 16 edges per warp

    // GEMM1: h1 = relu(h0 @ Wh + b_h)  [128e x 64j x 64k]
    // 1 j per lane: j = (w&1)*32 + lane. Weight load shared by 16 edges.
    {
        int j1 = (w & 1) * 32 + lane;
        u64 acc1[16];
#pragma unroll
        for (int i = 0; i < 16; i++) acc1[i] = 0ull;

#pragma unroll 1
        for (int k = 0; k < 64; k += 4) {
            ulonglong2 wp = *(const ulonglong2*)&whT[j1 * WSTRIDE + k];
#pragma unroll
            for (int i = 0; i < 16; i++) {
                ulonglong2 hv = *(const ulonglong2*)&hb[(e0 + i) * HSTRIDE + k]; // broadcast
                fma2(acc1[i], hv.x, wp.x);
                fma2(acc1[i], hv.y, wp.y);
            }
        }
        __syncthreads();   // all h0 reads complete before h1 overwrites buffer
        float bj = bh[j1];
#pragma unroll
        for (int i = 0; i < 16; i++)
            hb[(e0 + i) * HSTRIDE + j1] = fmaxf(bj + sum2(acc1[i]), 0.f);
    }
    __syncthreads();

    // GEMM2 + scatter: h2 = relu(h1 @ Wout + b_out); red-add into sn[dst]
    // 2 j per lane: j = (w&1)*64 + lane + {0,32}. 16 edges per warp.
    {
        int j2 = (w & 1) * 64 + lane;
        u64 acc2[16][2];
#pragma unroll
        for (int i = 0; i < 16; i++) { acc2[i][0] = 0ull; acc2[i][1] = 0ull; }

#pragma unroll 1
        for (int k = 0; k < 64; k += 4) {
            ulonglong2 wp0 = *(const ulonglong2*)&woT[j2 * WSTRIDE + k];
            ulonglong2 wp1 = *(const ulonglong2*)&woT[(j2 + 32) * WSTRIDE + k];
#pragma unroll
            for (int i = 0; i < 16; i++) {
                ulonglong2 hv = *(const ulonglong2*)&hb[(e0 + i) * HSTRIDE + k]; // broadcast
                fma2(acc2[i][0], hv.x, wp0.x);
                fma2(acc2[i][0], hv.y, wp0.y);
                fma2(acc2[i][1], hv.x, wp1.x);
                fma2(acc2[i][1], hv.y, wp1.y);
            }
        }

        float b0 = bo[j2], b1 = bo[j2 + 32];
#pragma unroll
        for (int i = 0; i < 16; i++) {
            float* row = sn + (size_t)dsts[e0 + i] * DD;
            atomicAdd(row + j2,      fmaxf(b0 + sum2(acc2[i][0]), 0.f));
            atomicAdd(row + j2 + 32, fmaxf(b1 + sum2(acc2[i][1]), 0.f));
        }
    }
}

// ---------------- molecule pooling ----------------
__global__ void pool_kernel(const float* __restrict__ s, const void* __restrict__ molp,
                            float* __restrict__ mol) {
    int i = blockIdx.x * blockDim.x + threadIdx.x;
    int stride = gridDim.x * blockDim.x;
    for (; i < NN * 32; i += stride) {
        int atom = i >> 5, q = (i & 31) * 4;
        int m = load_idx(molp, atom);
        float4 v = *(const float4*)&s[(size_t)atom * DD + q];
        float* row = &mol[m * DD + q];
        atomicAdd(row + 0, v.x);
        atomicAdd(row + 1, v.y);
        atomicAdd(row + 2, v.z);
        atomicAdd(row + 3, v.w);
    }
}

// ---------------- final MLP: one block per molecule, 64 threads ----------------
__global__ void mlp_kernel(const float* __restrict__ mol,
                           const float* __restrict__ w1, const float* __restrict__ b1,
                           const float* __restrict__ w2, const float* __restrict__ b2,
                           const float* __restrict__ w3, const float* __restrict__ b3,
                           float* __restrict__ out) {
    __shared__ float mr[128], a1[64], a2[64];
    int m = blockIdx.x, tid = threadIdx.x;
    mr[tid]      = mol[m * DD + tid];
    mr[tid + 64] = mol[m * DD + tid + 64];
    __syncthreads();
    float acc = b1[tid];
    for (int k = 0; k < 128; k++) acc = fmaf(mr[k], w1[k * 64 + tid], acc);
    a1[tid] = fmaxf(acc, 0.f);
    __syncthreads();
    acc = b2[tid];
    for (int k = 0; k < 64; k++) acc = fmaf(a1[k], w2[k * 64 + tid], acc);
    a2[tid] = fmaxf(acc, 0.f);
    __syncthreads();
    if (tid < OUTC) {
        acc = b3[tid];
        for (int k = 0; k < 64; k++) acc = fmaf(a2[k], w3[k * OUTC + tid], acc);
        out[m * OUTC + tid] = acc;
    }
}

// ---------------- host launcher ----------------
extern "C" void kernel_launch(void* const* d_in, const int* in_sizes, int n_in,
                              void* d_out, int out_size) {
    (void)in_sizes; (void)n_in; (void)out_size;
    const float* states = (const float*)d_in[0];
    const float* Win    = (const float*)d_in[1];
    const float* b_in   = (const float*)d_in[2];
    const float* Wh     = (const float*)d_in[3];
    const float* b_h    = (const float*)d_in[4];
    const float* Wout   = (const float*)d_in[5];
    const float* b_out  = (const float*)d_in[6];
    const float* fc1_w  = (const float*)d_in[7];
    const float* fc1_b  = (const float*)d_in[8];
    const float* fc2_w  = (const float*)d_in[9];
    const float* fc2_b  = (const float*)d_in[10];
    const float* out_w  = (const float*)d_in[11];
    const float* out_b  = (const float*)d_in[12];
    const void*  src    = d_in[13];
    const void*  dst    = d_in[14];
    const void*  molid  = d_in[15];
    float* out = (float*)d_out;

    cudaFuncSetAttribute(precompute_kernel,
        cudaFuncAttributeMaxDynamicSharedMemorySize, PC_SMEM_BYTES);
    cudaFuncSetAttribute(edge_kernel,
        cudaFuncAttributeMaxDynamicSharedMemorySize, EDGE_SMEM_BYTES);

    float *s1, *s2, *ab, *mol;
    cudaGetSymbolAddress((void**)&s1, g_s1);
    cudaGetSymbolAddress((void**)&s2, g_s2);
    cudaGetSymbolAddress((void**)&ab, g_Abuf);
    cudaGetSymbolAddress((void**)&mol, g_mol);

    detect_kernel<<<1, 32>>>((const int*)src);

    const int pc_grid = (NN + 63) / 64;        // 782
    const int e_grid  = EE / 128;              // 3125
    const int z_grid  = 296;

    const float* sin = states;
    float* bufs[2] = {s1, s2};
    for (int t = 0; t < 3; t++) {
        float* sout = bufs[t & 1];
        precompute_kernel<<<pc_grid, 256, PC_SMEM_BYTES>>>(sin, ab, Win + (size_t)t * 2 * DD * 64);
        zero_kernel<<<z_grid, 256>>>((float4*)sout, NN * DD / 4);
        edge_kernel<<<e_grid, 512, EDGE_SMEM_BYTES>>>(
            ab, sout, src, dst,
            Wh + (size_t)t * 64 * 64, b_h + (size_t)t * 64,
            Wout + (size_t)t * 64 * DD, b_out + (size_t)t * DD,
            b_in + (size_t)t * 64);
        sin = sout;
    }

    zero_kernel<<<8, 256>>>((float4*)mol, NMOL * DD / 4);
    pool_kernel<<<592, 256>>>(sin, molid, mol);
    mlp_kernel<<<NMOL, 64>>>(mol, fc1_w, fc1_b, fc2_w, fc2_b, out_w, out_b, out);
}

// round 9
// speedup vs baseline: 1.1260x; 1.1260x over previous
#include <cuda_runtime.h>
#include <cuda_bf16.h>

#define NN   50000
#define DD   128
#define EE   400000
#define NMOL 256
#define OUTC 32

#define NTILES (EE / 64)   // 6250
#define TPB 4              // tiles per block

typedef unsigned long long u64;

// ---------------- device scratch (no allocations allowed) ----------------
__device__ float g_s1[NN * DD];
__device__ float g_s2[NN * DD];
__device__ float g_Abuf[NN * DD];
__device__ float g_mol[NMOL * DD];
__device__ int   g_is64;

// ---------------- f32x2 helpers ----------------
__device__ __forceinline__ void fma2(u64 &d, u64 a, u64 b) {
    asm("fma.rn.f32x2 %0, %1, %2, %0;" : "+l"(d) : "l"(a), "l"(b));
}
__device__ __forceinline__ float sum2(u64 v) {
    float lo, hi;
    asm("mov.b64 {%0,%1}, %2;" : "=f"(lo), "=f"(hi) : "l"(v));
    return lo + hi;
}

// ---------------- index width detection (int32 vs int64) ----------------
__global__ void detect_kernel(const int* p) {
    if (threadIdx.x == 0) {
        int all0 = 1;
        for (int i = 0; i < 64; i++)
            if (p[2 * i + 1] != 0) { all0 = 0; break; }
        g_is64 = all0;  // int64 little-endian: high words all zero (values < N)
    }
}
__device__ __forceinline__ int load_idx(const void* p, int i) {
    if (g_is64) return (int)((const long long*)p)[i];
    return ((const int*)p)[i];
}

// ---------------- zero fill (vectorized) ----------------
__global__ void zero_kernel(float4* p, int n4) {
    int i = blockIdx.x * blockDim.x + threadIdx.x;
    int stride = gridDim.x * blockDim.x;
    float4 z = make_float4(0.f, 0.f, 0.f, 0.f);
    for (; i < n4; i += stride) p[i] = z;
}

// ================= precompute: A = S @ [Win_top | Win_bot]  ([N,128]x[128,128]) ======
#define PC_STRIDE 132
#define PC_SMEM_BYTES ((128 * PC_STRIDE + 64 * PC_STRIDE) * 4)

__global__ __launch_bounds__(256, 2)
void precompute_kernel(const float* __restrict__ s, float* __restrict__ out,
                       const float* __restrict__ Win_t) {
    extern __shared__ float sm[];
    float* wT = sm;                        // [128 j][132]
    float* ss = sm + 128 * PC_STRIDE;      // [64 a][132]
    int tid = threadIdx.x;
    int abase = blockIdx.x * 64;

    for (int i = tid; i < 128 * 128; i += 256) {
        int k = i >> 7, j = i & 127;
        float v = (j < 64) ? Win_t[k * 64 + j] : Win_t[(128 + k) * 64 + (j - 64)];
        wT[j * PC_STRIDE + k] = v;
    }
    for (int i = tid; i < 64 * 32; i += 256) {
        int a = i >> 5, kq = (i & 31) * 4;
        int atom = abase + a;
        float4 v = (atom < NN) ? *(const float4*)&s[(size_t)atom * DD + kq]
                               : make_float4(0.f, 0.f, 0.f, 0.f);
        *(float4*)&ss[a * PC_STRIDE + kq] = v;
    }
    __syncthreads();

    int jg = tid & 31;
    int a0 = (tid >> 5) * 8;
    u64 acc[8][4];
#pragma unroll
    for (int i = 0; i < 8; i++)
#pragma unroll
        for (int c = 0; c < 4; c++) acc[i][c] = 0ull;

#pragma unroll 2
    for (int k = 0; k < 128; k += 4) {
        ulonglong2 wp[4];
#pragma unroll
        for (int c = 0; c < 4; c++)
            wp[c] = *(const ulonglong2*)&wT[(jg + 32 * c) * PC_STRIDE + k];
#pragma unroll
        for (int h = 0; h < 2; h++) {
#pragma unroll
            for (int i = 0; i < 4; i++) {
                int r = h * 4 + i;
                ulonglong2 hv = *(const ulonglong2*)&ss[(a0 + r) * PC_STRIDE + k];
#pragma unroll
                for (int c = 0; c < 4; c++) {
                    fma2(acc[r][c], hv.x, wp[c].x);
                    fma2(acc[r][c], hv.y, wp[c].y);
                }
            }
        }
    }

#pragma unroll
    for (int i = 0; i < 8; i++) {
        int atom = abase + a0 + i;
        if (atom < NN) {
#pragma unroll
            for (int c = 0; c < 4; c++)
                out[(size_t)atom * DD + jg + 32 * c] = sum2(acc[i][c]);
        }
    }
}

// ================= edge kernel: 4 tiles of 64 edges per block, 256 threads ============
// Weights staged once per block (4 tiles). Next tile's gathers are issued before
// GEMM2 and combined/stored after it (double-buffered h), hiding L2 latency.
#define WSTRIDE 68
#define HSTRIDE 68
#define ES_WHT 0
#define ES_WOT (ES_WHT + 64 * WSTRIDE)     // 4352
#define ES_HA  (ES_WOT + 128 * WSTRIDE)    // 13056
#define ES_HB  (ES_HA + 64 * HSTRIDE)      // 17408
#define ES_BH  (ES_HB + 64 * HSTRIDE)      // 21760
#define ES_BO  (ES_BH + 64)                // 21824
#define ES_BI  (ES_BO + 128)               // 21952
#define ES_TOT (ES_BI + 64)                // 22016
#define EDGE_SMEM_BYTES (ES_TOT * 4)       // 88064 B -> 2 blocks/SM

__global__ __launch_bounds__(256, 2)
void edge_kernel(const float* __restrict__ A, float* __restrict__ sn,
                 const void* __restrict__ srcp, const void* __restrict__ dstp,
                 const float* __restrict__ Wh_t, const float* __restrict__ bh_t,
                 const float* __restrict__ Wo_t, const float* __restrict__ bo_t,
                 const float* __restrict__ bi_t) {
    extern __shared__ float sm[];
    float* whT = sm + ES_WHT;   // [64 j][68]
    float* woT = sm + ES_WOT;   // [128 j][68]
    float* bh  = sm + ES_BH;
    float* bo  = sm + ES_BO;
    float* bi  = sm + ES_BI;
    int tid = threadIdx.x;

    // stage weights + biases (once per block = once per 4 tiles)
    for (int i = tid; i < 64 * 64; i += 256) {
        int k = i >> 6, j = i & 63;
        whT[j * WSTRIDE + k] = Wh_t[i];
    }
    for (int i = tid; i < 64 * 128; i += 256) {
        int k = i >> 7, j = i & 127;
        woT[j * WSTRIDE + k] = Wo_t[i];
    }
    if (tid < 64) { bh[tid] = bh_t[tid]; bi[tid] = bi_t[tid]; }
    if (tid >= 64 && tid < 192) bo[tid - 64] = bo_t[tid - 64];
    __syncthreads();   // weights/biases visible

    float* cur = sm + ES_HA;
    float* nxt = sm + ES_HB;

    const int tb0 = blockIdx.x * TPB;
    const int e  = tid >> 2;            // gather role: 4 threads per edge
    const int j0 = (tid & 3) * 16;

    // ---- prologue: gather tile tb0 -> cur (h0) ----
    if (tb0 < NTILES) {
        int eg = tb0 * 64 + e;
        int d = load_idx(dstp, eg);
        int s = load_idx(srcp, eg);
        const float* ad = A + (size_t)d * DD + j0;
        const float* as = A + (size_t)s * DD + 64 + j0;
#pragma unroll
        for (int v = 0; v < 16; v += 4) {
            float4 x = *(const float4*)(ad + v);
            float4 y = *(const float4*)(as + v);
            float4 b = *(const float4*)(bi + j0 + v);
            float4 r;
            r.x = fmaxf(x.x + y.x + b.x, 0.f);
            r.y = fmaxf(x.y + y.y + b.y, 0.f);
            r.z = fmaxf(x.z + y.z + b.z, 0.f);
            r.w = fmaxf(x.w + y.w + b.w, 0.f);
            *(float4*)&cur[e * HSTRIDE + j0 + v] = r;
        }
    }

    for (int t = 0; t < TPB; t++) {
        int tb = tb0 + t;
        if (tb >= NTILES) break;        // block-uniform
        bool pf = (t + 1 < TPB) && (tb + 1 < NTILES);

        __syncthreads();                // cur h0 ready

        // ---- GEMM1: h1 = relu(h0 @ Wh + b_h)  [64e x 64j x 64k] ----
        {
            int jg = tid & 15;           // j in {jg, jg+16, jg+32, jg+48}
            int e0 = (tid >> 4) * 4;     // 4 edges
            u64 acc[4][4];
#pragma unroll
            for (int i = 0; i < 4; i++)
#pragma unroll
                for (int c = 0; c < 4; c++) acc[i][c] = 0ull;

#pragma unroll 4
            for (int k = 0; k < 64; k += 4) {
                ulonglong2 wp[4];
#pragma unroll
                for (int c = 0; c < 4; c++)
                    wp[c] = *(const ulonglong2*)&whT[(jg + 16 * c) * WSTRIDE + k];
#pragma unroll
                for (int i = 0; i < 4; i++) {
                    ulonglong2 hv = *(const ulonglong2*)&cur[(e0 + i) * HSTRIDE + k];
#pragma unroll
                    for (int c = 0; c < 4; c++) {
                        fma2(acc[i][c], hv.x, wp[c].x);
                        fma2(acc[i][c], hv.y, wp[c].y);
                    }
                }
            }
            __syncthreads();   // h0 reads complete before h1 overwrites
#pragma unroll
            for (int i = 0; i < 4; i++)
#pragma unroll
                for (int c = 0; c < 4; c++) {
                    int j = jg + 16 * c;
                    cur[(e0 + i) * HSTRIDE + j] = fmaxf(bh[j] + sum2(acc[i][c]), 0.f);
                }
        }
        __syncthreads();       // h1 visible

        // ---- prefetch next tile's gather data (consumed after GEMM2) ----
        float4 px[4], py[4];
        if (pf) {
            int eg = (tb + 1) * 64 + e;
            int d = load_idx(dstp, eg);
            int s = load_idx(srcp, eg);
            const float* ad = A + (size_t)d * DD + j0;
            const float* as = A + (size_t)s * DD + 64 + j0;
#pragma unroll
            for (int v = 0; v < 4; v++) {
                px[v] = *(const float4*)(ad + v * 4);
                py[v] = *(const float4*)(as + v * 4);
            }
        }

        // ---- GEMM2 + scatter: h2 = relu(h1 @ Wout + b_out); red-add sn[dst] ----
        {
            int jg = tid & 31;           // j in {jg, jg+32, jg+64, jg+96}
            int e0 = (tid >> 5) * 8;     // 8 edges
            u64 acc[8][4];
#pragma unroll
            for (int i = 0; i < 8; i++)
#pragma unroll
                for (int c = 0; c < 4; c++) acc[i][c] = 0ull;

#pragma unroll 2
            for (int k = 0; k < 64; k += 4) {
                ulonglong2 wp[4];
#pragma unroll
                for (int c = 0; c < 4; c++)
                    wp[c] = *(const ulonglong2*)&woT[(jg + 32 * c) * WSTRIDE + k];
#pragma unroll
                for (int h = 0; h < 2; h++) {
#pragma unroll
                    for (int i = 0; i < 4; i++) {
                        int r = h * 4 + i;
                        ulonglong2 hv = *(const ulonglong2*)&cur[(e0 + r) * HSTRIDE + k];
#pragma unroll
                        for (int c = 0; c < 4; c++) {
                            fma2(acc[r][c], hv.x, wp[c].x);
                            fma2(acc[r][c], hv.y, wp[c].y);
                        }
                    }
                }
            }

#pragma unroll
            for (int i = 0; i < 8; i++) {
                int de = load_idx(dstp, tb * 64 + e0 + i);   // L1-hot
                float* row = sn + (size_t)de * DD;
#pragma unroll
                for (int c = 0; c < 4; c++) {
                    int j = jg + 32 * c;
                    float v = fmaxf(bo[j] + sum2(acc[i][c]), 0.f);
                    atomicAdd(row + j, v);   // REDG, warp-coalesced over j
                }
            }
        }

        // ---- combine prefetched gather -> nxt (h0 of next tile) ----
        if (pf) {
#pragma unroll
            for (int v = 0; v < 4; v++) {
                int j = j0 + v * 4;
                float4 b = *(const float4*)(bi + j);
                float4 r;
                r.x = fmaxf(px[v].x + py[v].x + b.x, 0.f);
                r.y = fmaxf(px[v].y + py[v].y + b.y, 0.f);
                r.z = fmaxf(px[v].z + py[v].z + b.z, 0.f);
                r.w = fmaxf(px[v].w + py[v].w + b.w, 0.f);
                *(float4*)&nxt[e * HSTRIDE + j] = r;
            }
        }

        float* tmp = cur; cur = nxt; nxt = tmp;
    }
}

// ---------------- molecule pooling ----------------
__global__ void pool_kernel(const float* __restrict__ s, const void* __restrict__ molp,
                            float* __restrict__ mol) {
    int i = blockIdx.x * blockDim.x + threadIdx.x;
    int stride = gridDim.x * blockDim.x;
    for (; i < NN * 32; i += stride) {
        int atom = i >> 5, q = (i & 31) * 4;
        int m = load_idx(molp, atom);
        float4 v = *(const float4*)&s[(size_t)atom * DD + q];
        float* row = &mol[m * DD + q];
        atomicAdd(row + 0, v.x);
        atomicAdd(row + 1, v.y);
        atomicAdd(row + 2, v.z);
        atomicAdd(row + 3, v.w);
    }
}

// ---------------- final MLP: one block per molecule, 64 threads ----------------
__global__ void mlp_kernel(const float* __restrict__ mol,
                           const float* __restrict__ w1, const float* __restrict__ b1,
                           const float* __restrict__ w2, const float* __restrict__ b2,
                           const float* __restrict__ w3, const float* __restrict__ b3,
                           float* __restrict__ out) {
    __shared__ float mr[128], a1[64], a2[64];
    int m = blockIdx.x, tid = threadIdx.x;
    mr[tid]      = mol[m * DD + tid];
    mr[tid + 64] = mol[m * DD + tid + 64];
    __syncthreads();
    float acc = b1[tid];
    for (int k = 0; k < 128; k++) acc = fmaf(mr[k], w1[k * 64 + tid], acc);
    a1[tid] = fmaxf(acc, 0.f);
    __syncthreads();
    acc = b2[tid];
    for (int k = 0; k < 64; k++) acc = fmaf(a1[k], w2[k * 64 + tid], acc);
    a2[tid] = fmaxf(acc, 0.f);
    __syncthreads();
    if (tid < OUTC) {
        acc = b3[tid];
        for (int k = 0; k < 64; k++) acc = fmaf(a2[k], w3[k * OUTC + tid], acc);
        out[m * OUTC + tid] = acc;
    }
}

// ---------------- host launcher ----------------
extern "C" void kernel_launch(void* const* d_in, const int* in_sizes, int n_in,
                              void* d_out, int out_size) {
    (void)in_sizes; (void)n_in; (void)out_size;
    const float* states = (const float*)d_in[0];
    const float* Win    = (const float*)d_in[1];
    const float* b_in   = (const float*)d_in[2];
    const float* Wh     = (const float*)d_in[3];
    const float* b_h    = (const float*)d_in[4];
    const float* Wout   = (const float*)d_in[5];
    const float* b_out  = (const float*)d_in[6];
    const float* fc1_w  = (const float*)d_in[7];
    const float* fc1_b  = (const float*)d_in[8];
    const float* fc2_w  = (const float*)d_in[9];
    const float* fc2_b  = (const float*)d_in[10];
    const float* out_w  = (const float*)d_in[11];
    const float* out_b  = (const float*)d_in[12];
    const void*  src    = d_in[13];
    const void*  dst    = d_in[14];
    const void*  molid  = d_in[15];
    float* out = (float*)d_out;

    cudaFuncSetAttribute(precompute_kernel,
        cudaFuncAttributeMaxDynamicSharedMemorySize, PC_SMEM_BYTES);
    cudaFuncSetAttribute(edge_kernel,
        cudaFuncAttributeMaxDynamicSharedMemorySize, EDGE_SMEM_BYTES);

    float *s1, *s2, *ab, *mol;
    cudaGetSymbolAddress((void**)&s1, g_s1);
    cudaGetSymbolAddress((void**)&s2, g_s2);
    cudaGetSymbolAddress((void**)&ab, g_Abuf);
    cudaGetSymbolAddress((void**)&mol, g_mol);

    detect_kernel<<<1, 32>>>((const int*)src);

    const int pc_grid = (NN + 63) / 64;                // 782
    const int e_grid  = (NTILES + TPB - 1) / TPB;      // 1563
    const int z_grid  = 296;

    const float* sin = states;
    float* bufs[2] = {s1, s2};
    for (int t = 0; t < 3; t++) {
        float* sout = bufs[t & 1];
        precompute_kernel<<<pc_grid, 256, PC_SMEM_BYTES>>>(sin, ab, Win + (size_t)t * 2 * DD * 64);
        zero_kernel<<<z_grid, 256>>>((float4*)sout, NN * DD / 4);
        edge_kernel<<<e_grid, 256, EDGE_SMEM_BYTES>>>(
            ab, sout, src, dst,
            Wh + (size_t)t * 64 * 64, b_h + (size_t)t * 64,
            Wout + (size_t)t * 64 * DD, b_out + (size_t)t * DD,
            b_in + (size_t)t * 64);
        sin = sout;
    }

    zero_kernel<<<8, 256>>>((float4*)mol, NMOL * DD / 4);
    pool_kernel<<<592, 256>>>(sin, molid, mol);
    mlp_kernel<<<NMOL, 64>>>(mol, fc1_w, fc1_b, fc2_w, fc2_b, out_w, out_b, out);
}

// round 11
// speedup vs baseline: 1.1369x; 1.0097x over previous
#include <cuda_runtime.h>
#include <cuda_bf16.h>

#define NN   50000
#define DD   128
#define EE   400000
#define NMOL 256
#define OUTC 32

typedef unsigned long long u64;

// ---------------- device scratch (no allocations allowed) ----------------
__device__ float g_s1[NN * DD];
__device__ float g_s2[NN * DD];
__device__ float g_Abuf[NN * DD];
__device__ float g_mol[NMOL * DD];
__device__ int   g_is64;

// ---------------- f32x2 helpers ----------------
__device__ __forceinline__ void fma2(u64 &d, u64 a, u64 b) {
    asm("fma.rn.f32x2 %0, %1, %2, %0;" : "+l"(d) : "l"(a), "l"(b));
}
__device__ __forceinline__ float sum2(u64 v) {
    float lo, hi;
    asm("mov.b64 {%0,%1}, %2;" : "=f"(lo), "=f"(hi) : "l"(v));
    return lo + hi;
}

// ---------------- index width detection (int32 vs int64) ----------------
__global__ void detect_kernel(const int* p) {
    if (threadIdx.x == 0) {
        int all0 = 1;
        for (int i = 0; i < 64; i++)
            if (p[2 * i + 1] != 0) { all0 = 0; break; }
        g_is64 = all0;  // int64 little-endian: high words all zero (values < N)
    }
}
__device__ __forceinline__ int load_idx(const void* p, int i) {
    if (g_is64) return (int)((const long long*)p)[i];
    return ((const int*)p)[i];
}

// ---------------- zero fill (vectorized) ----------------
__global__ void zero_kernel(float4* p, int n4) {
    int i = blockIdx.x * blockDim.x + threadIdx.x;
    int stride = gridDim.x * blockDim.x;
    float4 z = make_float4(0.f, 0.f, 0.f, 0.f);
    for (; i < n4; i += stride) p[i] = z;
}

// ================= precompute: A = S @ [Win_top | Win_bot]  ([N,128]x[128,128]) ======
#define PC_STRIDE 132
#define PC_SMEM_BYTES ((128 * PC_STRIDE + 64 * PC_STRIDE) * 4)

__global__ __launch_bounds__(256, 2)
void precompute_kernel(const float* __restrict__ s, float* __restrict__ out,
                       const float* __restrict__ Win_t) {
    extern __shared__ float sm[];
    float* wT = sm;                        // [128 j][132]
    float* ss = sm + 128 * PC_STRIDE;      // [64 a][132]
    int tid = threadIdx.x;
    int abase = blockIdx.x * 64;

    for (int i = tid; i < 128 * 128; i += 256) {
        int k = i >> 7, j = i & 127;
        float v = (j < 64) ? Win_t[k * 64 + j] : Win_t[(128 + k) * 64 + (j - 64)];
        wT[j * PC_STRIDE + k] = v;
    }
    for (int i = tid; i < 64 * 32; i += 256) {
        int a = i >> 5, kq = (i & 31) * 4;
        int atom = abase + a;
        float4 v = (atom < NN) ? *(const float4*)&s[(size_t)atom * DD + kq]
                               : make_float4(0.f, 0.f, 0.f, 0.f);
        *(float4*)&ss[a * PC_STRIDE + kq] = v;
    }
    __syncthreads();

    int jg = tid & 31;
    int a0 = (tid >> 5) * 8;
    u64 acc[8][4];
#pragma unroll
    for (int i = 0; i < 8; i++)
#pragma unroll
        for (int c = 0; c < 4; c++) acc[i][c] = 0ull;

#pragma unroll 2
    for (int k = 0; k < 128; k += 4) {
        ulonglong2 wp[4];
#pragma unroll
        for (int c = 0; c < 4; c++)
            wp[c] = *(const ulonglong2*)&wT[(jg + 32 * c) * PC_STRIDE + k];
#pragma unroll
        for (int h = 0; h < 2; h++) {
#pragma unroll
            for (int i = 0; i < 4; i++) {
                int r = h * 4 + i;
                ulonglong2 hv = *(const ulonglong2*)&ss[(a0 + r) * PC_STRIDE + k];
#pragma unroll
                for (int c = 0; c < 4; c++) {
                    fma2(acc[r][c], hv.x, wp[c].x);
                    fma2(acc[r][c], hv.y, wp[c].y);
                }
            }
        }
    }

#pragma unroll
    for (int i = 0; i < 8; i++) {
        int atom = abase + a0 + i;
        if (atom < NN) {
#pragma unroll
            for (int c = 0; c < 4; c++)
                out[(size_t)atom * DD + jg + 32 * c] = sum2(acc[i][c]);
        }
    }
}

// ================= edge kernel: 64 edges per block, 256 threads, 3 blocks/SM =========
// Single h buffer (h0 overwritten by h1). GEMM2 runs as two j-half passes so the
// accumulator fits the 85-reg budget of occupancy 3.
#define WSTRIDE 68
#define HSTRIDE 68
#define ES_WHT 0
#define ES_WOT (ES_WHT + 64 * WSTRIDE)     // 4352
#define ES_H   (ES_WOT + 128 * WSTRIDE)    // 13056
#define ES_BH  (ES_H + 64 * HSTRIDE)       // 17408
#define ES_BO  (ES_BH + 64)                // 17472
#define ES_BI  (ES_BO + 128)               // 17600
#define ES_IDX (ES_BI + 64)                // 17664
#define ES_TOT (ES_IDX + 128)              // 17792
#define EDGE_SMEM_BYTES (ES_TOT * 4)       // 71168 B -> 3 blocks/SM

__global__ __launch_bounds__(256, 3)
void edge_kernel(const float* __restrict__ A, float* __restrict__ sn,
                 const void* __restrict__ srcp, const void* __restrict__ dstp,
                 const float* __restrict__ Wh_t, const float* __restrict__ bh_t,
                 const float* __restrict__ Wo_t, const float* __restrict__ bo_t,
                 const float* __restrict__ bi_t) {
    extern __shared__ float sm[];
    float* whT = sm + ES_WHT;   // [64 j][68]
    float* woT = sm + ES_WOT;   // [128 j][68]
    float* hb  = sm + ES_H;     // [64 e][68]  (h0, then h1)
    float* bh  = sm + ES_BH;
    float* bo  = sm + ES_BO;
    float* bi  = sm + ES_BI;
    int*   dsts = (int*)(sm + ES_IDX);
    int*   srcs = dsts + 64;
    int tid = threadIdx.x;
    int eb = blockIdx.x * 64;

    for (int i = tid; i < 64 * 64; i += 256) {
        int k = i >> 6, j = i & 63;
        whT[j * WSTRIDE + k] = Wh_t[i];
    }
    for (int i = tid; i < 64 * 128; i += 256) {
        int k = i >> 7, j = i & 127;
        woT[j * WSTRIDE + k] = Wo_t[i];
    }
    if (tid < 64) {
        bh[tid] = bh_t[tid];
        bi[tid] = bi_t[tid];
        dsts[tid] = load_idx(dstp, eb + tid);
        srcs[tid] = load_idx(srcp, eb + tid);
    }
    if (tid >= 64 && tid < 192) bo[tid - 64] = bo_t[tid - 64];
    __syncthreads();

    // layer 0: hb[e][j] = relu(A[dst][j] + A[src][64+j] + b_in[j]),  j<64
    {
        int e = tid >> 2;
        int j0 = (tid & 3) * 16;
        const float* ad = A + (size_t)dsts[e] * DD;
        const float* as = A + (size_t)srcs[e] * DD + 64;
#pragma unroll
        for (int v = 0; v < 16; v += 4) {
            int j = j0 + v;
            float4 x = *(const float4*)(ad + j);
            float4 y = *(const float4*)(as + j);
            float4 b = *(const float4*)(bi + j);
            float4 r;
            r.x = fmaxf(x.x + y.x + b.x, 0.f);
            r.y = fmaxf(x.y + y.y + b.y, 0.f);
            r.z = fmaxf(x.z + y.z + b.z, 0.f);
            r.w = fmaxf(x.w + y.w + b.w, 0.f);
            *(float4*)&hb[e * HSTRIDE + j] = r;
        }
    }
    __syncthreads();

    // GEMM1: h1 = relu(h0 @ Wh + b_h)   [64e x 64j x 64k], h1 overwrites h0
    {
        int jg = tid & 15;           // j in {jg, jg+16, jg+32, jg+48}
        int e0 = (tid >> 4) * 4;     // 4 edges
        u64 acc[4][4];
#pragma unroll
        for (int i = 0; i < 4; i++)
#pragma unroll
            for (int c = 0; c < 4; c++) acc[i][c] = 0ull;

#pragma unroll 4
        for (int k = 0; k < 64; k += 4) {
            ulonglong2 wp[4];
#pragma unroll
            for (int c = 0; c < 4; c++)
                wp[c] = *(const ulonglong2*)&whT[(jg + 16 * c) * WSTRIDE + k];
#pragma unroll
            for (int i = 0; i < 4; i++) {
                ulonglong2 hv = *(const ulonglong2*)&hb[(e0 + i) * HSTRIDE + k];
#pragma unroll
                for (int c = 0; c < 4; c++) {
                    fma2(acc[i][c], hv.x, wp[c].x);
                    fma2(acc[i][c], hv.y, wp[c].y);
                }
            }
        }
        __syncthreads();   // all h0 reads complete before h1 overwrites the buffer
#pragma unroll
        for (int i = 0; i < 4; i++)
#pragma unroll
            for (int c = 0; c < 4; c++) {
                int j = jg + 16 * c;
                hb[(e0 + i) * HSTRIDE + j] = fmaxf(bh[j] + sum2(acc[i][c]), 0.f);
            }
    }
    __syncthreads();

    // GEMM2 + scatter, two j-half passes: h2 = relu(h1 @ Wout + b_out); red-add sn[dst]
    {
        int jg = tid & 31;
        int e0 = (tid >> 5) * 8;     // 8 edges per thread group (warp-uniform)
#pragma unroll
        for (int jh = 0; jh < 2; jh++) {
            int ja = jh * 64 + jg;           // j in {ja, ja+32}
            u64 acc[8][2];
#pragma unroll
            for (int i = 0; i < 8; i++) { acc[i][0] = 0ull; acc[i][1] = 0ull; }

#pragma unroll 2
            for (int k = 0; k < 64; k += 4) {
                ulonglong2 wp0 = *(const ulonglong2*)&woT[ja * WSTRIDE + k];
                ulonglong2 wp1 = *(const ulonglong2*)&woT[(ja + 32) * WSTRIDE + k];
#pragma unroll
                for (int i = 0; i < 8; i++) {
                    ulonglong2 hv = *(const ulonglong2*)&hb[(e0 + i) * HSTRIDE + k]; // broadcast
                    fma2(acc[i][0], hv.x, wp0.x);
                    fma2(acc[i][0], hv.y, wp0.y);
                    fma2(acc[i][1], hv.x, wp1.x);
                    fma2(acc[i][1], hv.y, wp1.y);
                }
            }

            float b0 = bo[ja], b1 = bo[ja + 32];
#pragma unroll
            for (int i = 0; i < 8; i++) {
                float* row = sn + (size_t)dsts[e0 + i] * DD;
                atomicAdd(row + ja,      fmaxf(b0 + sum2(acc[i][0]), 0.f));
                atomicAdd(row + ja + 32, fmaxf(b1 + sum2(acc[i][1]), 0.f));
            }
        }
    }
}

// ---------------- molecule pooling ----------------
__global__ void pool_kernel(const float* __restrict__ s, const void* __restrict__ molp,
                            float* __restrict__ mol) {
    int i = blockIdx.x * blockDim.x + threadIdx.x;
    int stride = gridDim.x * blockDim.x;
    for (; i < NN * 32; i += stride) {
        int atom = i >> 5, q = (i & 31) * 4;
        int m = load_idx(molp, atom);
        float4 v = *(const float4*)&s[(size_t)atom * DD + q];
        float* row = &mol[m * DD + q];
        atomicAdd(row + 0, v.x);
        atomicAdd(row + 1, v.y);
        atomicAdd(row + 2, v.z);
        atomicAdd(row + 3, v.w);
    }
}

// ---------------- final MLP: one block per molecule, 64 threads ----------------
__global__ void mlp_kernel(const float* __restrict__ mol,
                           const float* __restrict__ w1, const float* __restrict__ b1,
                           const float* __restrict__ w2, const float* __restrict__ b2,
                           const float* __restrict__ w3, const float* __restrict__ b3,
                           float* __restrict__ out) {
    __shared__ float mr[128], a1[64], a2[64];
    int m = blockIdx.x, tid = threadIdx.x;
    mr[tid]      = mol[m * DD + tid];
    mr[tid + 64] = mol[m * DD + tid + 64];
    __syncthreads();
    float acc = b1[tid];
    for (int k = 0; k < 128; k++) acc = fmaf(mr[k], w1[k * 64 + tid], acc);
    a1[tid] = fmaxf(acc, 0.f);
    __syncthreads();
    acc = b2[tid];
    for (int k = 0; k < 64; k++) acc = fmaf(a1[k], w2[k * 64 + tid], acc);
    a2[tid] = fmaxf(acc, 0.f);
    __syncthreads();
    if (tid < OUTC) {
        acc = b3[tid];
        for (int k = 0; k < 64; k++) acc = fmaf(a2[k], w3[k * OUTC + tid], acc);
        out[m * OUTC + tid] = acc;
    }
}

// ---------------- host launcher ----------------
extern "C" void kernel_launch(void* const* d_in, const int* in_sizes, int n_in,
                              void* d_out, int out_size) {
    (void)in_sizes; (void)n_in; (void)out_size;
    const float* states = (const float*)d_in[0];
    const float* Win    = (const float*)d_in[1];
    const float* b_in   = (const float*)d_in[2];
    const float* Wh     = (const float*)d_in[3];
    const float* b_h    = (const float*)d_in[4];
    const float* Wout   = (const float*)d_in[5];
    const float* b_out  = (const float*)d_in[6];
    const float* fc1_w  = (const float*)d_in[7];
    const float* fc1_b  = (const float*)d_in[8];
    const float* fc2_w  = (const float*)d_in[9];
    const float* fc2_b  = (const float*)d_in[10];
    const float* out_w  = (const float*)d_in[11];
    const float* out_b  = (const float*)d_in[12];
    const void*  src    = d_in[13];
    const void*  dst    = d_in[14];
    const void*  molid  = d_in[15];
    float* out = (float*)d_out;

    cudaFuncSetAttribute(precompute_kernel,
        cudaFuncAttributeMaxDynamicSharedMemorySize, PC_SMEM_BYTES);
    cudaFuncSetAttribute(edge_kernel,
        cudaFuncAttributeMaxDynamicSharedMemorySize, EDGE_SMEM_BYTES);

    float *s1, *s2, *ab, *mol;
    cudaGetSymbolAddress((void**)&s1, g_s1);
    cudaGetSymbolAddress((void**)&s2, g_s2);
    cudaGetSymbolAddress((void**)&ab, g_Abuf);
    cudaGetSymbolAddress((void**)&mol, g_mol);

    detect_kernel<<<1, 32>>>((const int*)src);

    const int pc_grid = (NN + 63) / 64;        // 782
    const int e_grid  = EE / 64;               // 6250
    const int z_grid  = 296;

    const float* sin = states;
    float* bufs[2] = {s1, s2};
    for (int t = 0; t < 3; t++) {
        float* sout = bufs[t & 1];
        precompute_kernel<<<pc_grid, 256, PC_SMEM_BYTES>>>(sin, ab, Win + (size_t)t * 2 * DD * 64);
        zero_kernel<<<z_grid, 256>>>((float4*)sout, NN * DD / 4);
        edge_kernel<<<e_grid, 256, EDGE_SMEM_BYTES>>>(
            ab, sout, src, dst,
            Wh + (size_t)t * 64 * 64, b_h + (size_t)t * 64,
            Wout + (size_t)t * 64 * DD, b_out + (size_t)t * DD,
            b_in + (size_t)t * 64);
        sin = sout;
    }

    zero_kernel<<<8, 256>>>((float4*)mol, NMOL * DD / 4);
    pool_kernel<<<592, 256>>>(sin, molid, mol);
    mlp_kernel<<<NMOL, 64>>>(mol, fc1_w, fc1_b, fc2_w, fc2_b, out_w, out_b, out);
}

// round 16
// speedup vs baseline: 1.3319x; 1.1716x over previous
#include <cuda_runtime.h>
#include <cuda_bf16.h>
#include <mma.h>
#include <cstdint>

using namespace nvcuda;

#define NN   50000
#define DD   128
#define EE   400000
#define NMOL 256
#define OUTC 32

typedef unsigned long long u64;

// ---------------- device scratch (no allocations allowed) ----------------
__device__ float g_s1[NN * DD];
__device__ float g_s2[NN * DD];
__device__ float g_Abuf[NN * DD];
__device__ float g_mol[NMOL * DD];
__device__ int   g_is64;

// ---------------- f32x2 helpers (precompute kernel) ----------------
__device__ __forceinline__ void fma2(u64 &d, u64 a, u64 b) {
    asm("fma.rn.f32x2 %0, %1, %2, %0;" : "+l"(d) : "l"(a), "l"(b));
}
__device__ __forceinline__ float sum2(u64 v) {
    float lo, hi;
    asm("mov.b64 {%0,%1}, %2;" : "=f"(lo), "=f"(hi) : "l"(v));
    return lo + hi;
}

// ---------------- bf16 split helpers ----------------
__device__ __forceinline__ uint32_t pack_bf16(float lo, float hi) {
    uint32_t r;
    asm("cvt.rn.bf16x2.f32 %0, %1, %2;" : "=r"(r) : "f"(hi), "f"(lo));
    return r;
}
__device__ __forceinline__ float bf_lo(uint32_t p) { return __uint_as_float(p << 16); }
__device__ __forceinline__ float bf_hi(uint32_t p) { return __uint_as_float(p & 0xFFFF0000u); }
// split (a,b) -> hi bf16x2 + residual bf16x2
__device__ __forceinline__ void split2(float a, float b, uint32_t &h, uint32_t &l) {
    h = pack_bf16(a, b);
    l = pack_bf16(a - bf_lo(h), b - bf_hi(h));
}

// ---------------- index width detection (int32 vs int64) ----------------
__global__ void detect_kernel(const int* p) {
    if (threadIdx.x == 0) {
        int all0 = 1;
        for (int i = 0; i < 64; i++)
            if (p[2 * i + 1] != 0) { all0 = 0; break; }
        g_is64 = all0;
    }
}
__device__ __forceinline__ int load_idx(const void* p, int i) {
    if (g_is64) return (int)((const long long*)p)[i];
    return ((const int*)p)[i];
}

// ---------------- zero fill ----------------
__global__ void zero_kernel(float4* p, int n4) {
    int i = blockIdx.x * blockDim.x + threadIdx.x;
    int stride = gridDim.x * blockDim.x;
    float4 z = make_float4(0.f, 0.f, 0.f, 0.f);
    for (; i < n4; i += stride) p[i] = z;
}

// ================= precompute: A = S @ [Win_top | Win_bot] (f32x2, proven) ===========
#define PC_STRIDE 132
#define PC_SMEM_BYTES ((128 * PC_STRIDE + 64 * PC_STRIDE) * 4)

__global__ __launch_bounds__(256, 2)
void precompute_kernel(const float* __restrict__ s, float* __restrict__ out,
                       const float* __restrict__ Win_t) {
    extern __shared__ float sm[];
    float* wT = sm;
    float* ss = sm + 128 * PC_STRIDE;
    int tid = threadIdx.x;
    int abase = blockIdx.x * 64;

    for (int i = tid; i < 128 * 128; i += 256) {
        int k = i >> 7, j = i & 127;
        float v = (j < 64) ? Win_t[k * 64 + j] : Win_t[(128 + k) * 64 + (j - 64)];
        wT[j * PC_STRIDE + k] = v;
    }
    for (int i = tid; i < 64 * 32; i += 256) {
        int a = i >> 5, kq = (i & 31) * 4;
        int atom = abase + a;
        float4 v = (atom < NN) ? *(const float4*)&s[(size_t)atom * DD + kq]
                               : make_float4(0.f, 0.f, 0.f, 0.f);
        *(float4*)&ss[a * PC_STRIDE + kq] = v;
    }
    __syncthreads();

    int jg = tid & 31;
    int a0 = (tid >> 5) * 8;
    u64 acc[8][4];
#pragma unroll
    for (int i = 0; i < 8; i++)
#pragma unroll
        for (int c = 0; c < 4; c++) acc[i][c] = 0ull;

#pragma unroll 2
    for (int k = 0; k < 128; k += 4) {
        ulonglong2 wp[4];
#pragma unroll
        for (int c = 0; c < 4; c++)
            wp[c] = *(const ulonglong2*)&wT[(jg + 32 * c) * PC_STRIDE + k];
#pragma unroll
        for (int h = 0; h < 2; h++) {
#pragma unroll
            for (int i = 0; i < 4; i++) {
                int r = h * 4 + i;
                ulonglong2 hv = *(const ulonglong2*)&ss[(a0 + r) * PC_STRIDE + k];
#pragma unroll
                for (int c = 0; c < 4; c++) {
                    fma2(acc[r][c], hv.x, wp[c].x);
                    fma2(acc[r][c], hv.y, wp[c].y);
                }
            }
        }
    }

#pragma unroll
    for (int i = 0; i < 8; i++) {
        int atom = abase + a0 + i;
        if (atom < NN) {
#pragma unroll
            for (int c = 0; c < 4; c++)
                out[(size_t)atom * DD + jg + 32 * c] = sum2(acc[i][c]);
        }
    }
}

// ================= wmma edge kernel: 64 edges/block, 256 threads ======================
// bf16 hi/lo split GEMMs on the tensor pipe (HMMA via nvcuda::wmma, sm_103-legal).
// Smem layout (bytes). h tiles: [64 rows][72 bf16] (144B rows). Wh: [64 k][72], Wo: [64 k][136].
// f32 stages overlay the weight regions once those are dead.
#define HB_HI   0
#define HB_LO   9216
#define WH_HI   18432
#define WH_LO   27648
#define WO_HI   36864
#define WO_LO   54272
#define WE_SMEM 71680
#define STG1    WH_HI            // f32 [64][68] = 17408 <= 18432
#define STG2    WO_HI            // f32 [64][132] = 33792 <= 34816
#define H_LD    72
#define WO_LD   136

__global__ __launch_bounds__(256, 2)
void edge_kernel(const float* __restrict__ A, float* __restrict__ sn,
                 const void* __restrict__ srcp, const void* __restrict__ dstp,
                 const float* __restrict__ Wh_t, const float* __restrict__ bh_t,
                 const float* __restrict__ Wo_t, const float* __restrict__ bo_t,
                 const float* __restrict__ bi_t) {
    extern __shared__ char smc[];
    int tid = threadIdx.x;
    int w = tid >> 5, lane = tid & 31;
    int eb = blockIdx.x * 64;

    __nv_bfloat16* h_hi = (__nv_bfloat16*)(smc + HB_HI);
    __nv_bfloat16* h_lo = (__nv_bfloat16*)(smc + HB_LO);
    __nv_bfloat16* wh_hi = (__nv_bfloat16*)(smc + WH_HI);
    __nv_bfloat16* wh_lo = (__nv_bfloat16*)(smc + WH_LO);
    __nv_bfloat16* wo_hi = (__nv_bfloat16*)(smc + WO_HI);
    __nv_bfloat16* wo_lo = (__nv_bfloat16*)(smc + WO_LO);
    float* stg1 = (float*)(smc + STG1);
    float* stg2 = (float*)(smc + STG2);

    // ---- stage Wh (64k x 64j) as bf16 hi/lo, row-major k x j, ld 72 ----
    for (int i = tid; i < 64 * 32; i += 256) {
        int k = i >> 5, j = (i & 31) * 2;
        uint32_t h, l;
        split2(Wh_t[k * 64 + j], Wh_t[k * 64 + j + 1], h, l);
        *(uint32_t*)(smc + WH_HI + k * 144 + j * 2) = h;
        *(uint32_t*)(smc + WH_LO + k * 144 + j * 2) = l;
    }
    // ---- stage Wo (64k x 128j) as bf16 hi/lo, ld 136 ----
    for (int i = tid; i < 64 * 64; i += 256) {
        int k = i >> 6, j = (i & 63) * 2;
        uint32_t h, l;
        split2(Wo_t[k * 128 + j], Wo_t[k * 128 + j + 1], h, l);
        *(uint32_t*)(smc + WO_HI + k * 272 + j * 2) = h;
        *(uint32_t*)(smc + WO_LO + k * 272 + j * 2) = l;
    }

    // ---- gather + layer0 -> h0 bf16 hi/lo ----
    {
        int e = tid >> 2;
        int j0 = (tid & 3) * 16;
        int d = load_idx(dstp, eb + e);
        int s = load_idx(srcp, eb + e);
        const float* ad = A + (size_t)d * DD + j0;
        const float* as = A + (size_t)s * DD + 64 + j0;
#pragma unroll
        for (int q = 0; q < 4; q++) {
            float4 x = *(const float4*)(ad + 4 * q);
            float4 y = *(const float4*)(as + 4 * q);
            float4 b = *(const float4*)(bi_t + j0 + 4 * q);
            float r0 = fmaxf(x.x + y.x + b.x, 0.f);
            float r1 = fmaxf(x.y + y.y + b.y, 0.f);
            float r2 = fmaxf(x.z + y.z + b.z, 0.f);
            float r3 = fmaxf(x.w + y.w + b.w, 0.f);
            uint32_t h0, l0, h1, l1;
            split2(r0, r1, h0, l0);
            split2(r2, r3, h1, l1);
            int boff = e * 144 + (j0 + 4 * q) * 2;
            *(uint2*)(smc + HB_HI + boff) = make_uint2(h0, h1);
            *(uint2*)(smc + HB_LO + boff) = make_uint2(l0, l1);
        }
    }
    __syncthreads();

    // ---- GEMM1: [64e x 64j x 64k]  (16 tiles, 2 per warp, constant tm) ----
    {
        int tm = w >> 1;            // 2w>>2
        int tn0 = (2 * w) & 3;
        wmma::fragment<wmma::accumulator, 16, 16, 16, float> acc[2];
        wmma::fill_fragment(acc[0], 0.f);
        wmma::fill_fragment(acc[1], 0.f);
#pragma unroll
        for (int kk = 0; kk < 4; kk++) {
            wmma::fragment<wmma::matrix_a, 16, 16, 16, __nv_bfloat16, wmma::row_major> a_hi, a_lo;
            wmma::load_matrix_sync(a_hi, h_hi + tm * 16 * H_LD + kk * 16, H_LD);
            wmma::load_matrix_sync(a_lo, h_lo + tm * 16 * H_LD + kk * 16, H_LD);
#pragma unroll
            for (int q = 0; q < 2; q++) {
                wmma::fragment<wmma::matrix_b, 16, 16, 16, __nv_bfloat16, wmma::row_major> b_hi, b_lo;
                wmma::load_matrix_sync(b_hi, wh_hi + kk * 16 * H_LD + (tn0 + q) * 16, H_LD);
                wmma::load_matrix_sync(b_lo, wh_lo + kk * 16 * H_LD + (tn0 + q) * 16, H_LD);
                wmma::mma_sync(acc[q], a_hi, b_hi, acc[q]);
                wmma::mma_sync(acc[q], a_hi, b_lo, acc[q]);
                wmma::mma_sync(acc[q], a_lo, b_hi, acc[q]);
            }
        }
        __syncthreads();   // all GEMM1 reads of Wh done before stage1 overlays it
        wmma::store_matrix_sync(stg1 + tm * 16 * 68 + tn0 * 16, acc[0], 68, wmma::mem_row_major);
        wmma::store_matrix_sync(stg1 + tm * 16 * 68 + (tn0 + 1) * 16, acc[1], 68, wmma::mem_row_major);
    }
    __syncthreads();

    // ---- epilogue1: bias+relu, re-split -> h1 hi/lo (overwrites h0) ----
    {
        int e = tid >> 2;
        int j0 = (tid & 3) * 16;
#pragma unroll
        for (int q = 0; q < 4; q++) {
            int j = j0 + 4 * q;
            float4 v = *(const float4*)(stg1 + e * 68 + j);
            float4 b = *(const float4*)(bh_t + j);
            float r0 = fmaxf(v.x + b.x, 0.f);
            float r1 = fmaxf(v.y + b.y, 0.f);
            float r2 = fmaxf(v.z + b.z, 0.f);
            float r3 = fmaxf(v.w + b.w, 0.f);
            uint32_t h0, l0, h1, l1;
            split2(r0, r1, h0, l0);
            split2(r2, r3, h1, l1);
            int boff = e * 144 + j * 2;
            *(uint2*)(smc + HB_HI + boff) = make_uint2(h0, h1);
            *(uint2*)(smc + HB_LO + boff) = make_uint2(l0, l1);
        }
    }
    __syncthreads();

    // ---- GEMM2: [64e x 128j x 64k]  (32 tiles, 4 per warp, constant tm) ----
    {
        int tm = w >> 1;
        int tnb = (w & 1) * 4;
        wmma::fragment<wmma::accumulator, 16, 16, 16, float> acc[4];
#pragma unroll
        for (int q = 0; q < 4; q++) wmma::fill_fragment(acc[q], 0.f);
#pragma unroll
        for (int kk = 0; kk < 4; kk++) {
            wmma::fragment<wmma::matrix_a, 16, 16, 16, __nv_bfloat16, wmma::row_major> a_hi, a_lo;
            wmma::load_matrix_sync(a_hi, h_hi + tm * 16 * H_LD + kk * 16, H_LD);
            wmma::load_matrix_sync(a_lo, h_lo + tm * 16 * H_LD + kk * 16, H_LD);
#pragma unroll
            for (int q = 0; q < 4; q++) {
                wmma::fragment<wmma::matrix_b, 16, 16, 16, __nv_bfloat16, wmma::row_major> b_hi, b_lo;
                wmma::load_matrix_sync(b_hi, wo_hi + kk * 16 * WO_LD + (tnb + q) * 16, WO_LD);
                wmma::load_matrix_sync(b_lo, wo_lo + kk * 16 * WO_LD + (tnb + q) * 16, WO_LD);
                wmma::mma_sync(acc[q], a_hi, b_hi, acc[q]);
                wmma::mma_sync(acc[q], a_hi, b_lo, acc[q]);
                wmma::mma_sync(acc[q], a_lo, b_hi, acc[q]);
            }
        }
        __syncthreads();   // all GEMM2 reads of Wo done before stage2 overlays it
#pragma unroll
        for (int q = 0; q < 4; q++)
            wmma::store_matrix_sync(stg2 + tm * 16 * 132 + (tnb + q) * 16, acc[q], 132,
                                    wmma::mem_row_major);
    }
    __syncthreads();

    // ---- epilogue2: bias+relu + coalesced atomic scatter ----
    {
        int e0 = (tid >> 5) * 8;
#pragma unroll
        for (int i = 0; i < 8; i++) {
            int e = e0 + i;
            int de = load_idx(dstp, eb + e);    // L1-hot
            float* row = sn + (size_t)de * DD;
#pragma unroll
            for (int c = 0; c < 4; c++) {
                int j = lane + 32 * c;
                float v = fmaxf(stg2[e * 132 + j] + __ldg(bo_t + j), 0.f);
                atomicAdd(row + j, v);          // REDG, coalesced over j
            }
        }
    }
}

// ---------------- molecule pooling ----------------
__global__ void pool_kernel(const float* __restrict__ s, const void* __restrict__ molp,
                            float* __restrict__ mol) {
    int i = blockIdx.x * blockDim.x + threadIdx.x;
    int stride = gridDim.x * blockDim.x;
    for (; i < NN * 32; i += stride) {
        int atom = i >> 5, q = (i & 31) * 4;
        int m = load_idx(molp, atom);
        float4 v = *(const float4*)&s[(size_t)atom * DD + q];
        float* row = &mol[m * DD + q];
        atomicAdd(row + 0, v.x);
        atomicAdd(row + 1, v.y);
        atomicAdd(row + 2, v.z);
        atomicAdd(row + 3, v.w);
    }
}

// ---------------- final MLP ----------------
__global__ void mlp_kernel(const float* __restrict__ mol,
                           const float* __restrict__ w1, const float* __restrict__ b1,
                           const float* __restrict__ w2, const float* __restrict__ b2,
                           const float* __restrict__ w3, const float* __restrict__ b3,
                           float* __restrict__ out) {
    __shared__ float mr[128], a1[64], a2[64];
    int m = blockIdx.x, tid = threadIdx.x;
    mr[tid]      = mol[m * DD + tid];
    mr[tid + 64] = mol[m * DD + tid + 64];
    __syncthreads();
    float acc = b1[tid];
    for (int k = 0; k < 128; k++) acc = fmaf(mr[k], w1[k * 64 + tid], acc);
    a1[tid] = fmaxf(acc, 0.f);
    __syncthreads();
    acc = b2[tid];
    for (int k = 0; k < 64; k++) acc = fmaf(a1[k], w2[k * 64 + tid], acc);
    a2[tid] = fmaxf(acc, 0.f);
    __syncthreads();
    if (tid < OUTC) {
        acc = b3[tid];
        for (int k = 0; k < 64; k++) acc = fmaf(a2[k], w3[k * OUTC + tid], acc);
        out[m * OUTC + tid] = acc;
    }
}

// ---------------- host launcher ----------------
extern "C" void kernel_launch(void* const* d_in, const int* in_sizes, int n_in,
                              void* d_out, int out_size) {
    (void)in_sizes; (void)n_in; (void)out_size;
    const float* states = (const float*)d_in[0];
    const float* Win    = (const float*)d_in[1];
    const float* b_in   = (const float*)d_in[2];
    const float* Wh     = (const float*)d_in[3];
    const float* b_h    = (const float*)d_in[4];
    const float* Wout   = (const float*)d_in[5];
    const float* b_out  = (const float*)d_in[6];
    const float* fc1_w  = (const float*)d_in[7];
    const float* fc1_b  = (const float*)d_in[8];
    const float* fc2_w  = (const float*)d_in[9];
    const float* fc2_b  = (const float*)d_in[10];
    const float* out_w  = (const float*)d_in[11];
    const float* out_b  = (const float*)d_in[12];
    const void*  src    = d_in[13];
    const void*  dst    = d_in[14];
    const void*  molid  = d_in[15];
    float* out = (float*)d_out;

    cudaFuncSetAttribute(precompute_kernel,
        cudaFuncAttributeMaxDynamicSharedMemorySize, PC_SMEM_BYTES);
    cudaFuncSetAttribute(edge_kernel,
        cudaFuncAttributeMaxDynamicSharedMemorySize, WE_SMEM);

    float *s1, *s2, *ab, *mol;
    cudaGetSymbolAddress((void**)&s1, g_s1);
    cudaGetSymbolAddress((void**)&s2, g_s2);
    cudaGetSymbolAddress((void**)&ab, g_Abuf);
    cudaGetSymbolAddress((void**)&mol, g_mol);

    detect_kernel<<<1, 32>>>((const int*)src);

    const int pc_grid = (NN + 63) / 64;   // 782
    const int e_grid  = EE / 64;          // 6250
    const int z_grid  = 296;

    const float* sin = states;
    float* bufs[2] = {s1, s2};
    for (int t = 0; t < 3; t++) {
        float* sout = bufs[t & 1];
        precompute_kernel<<<pc_grid, 256, PC_SMEM_BYTES>>>(sin, ab, Win + (size_t)t * 2 * DD * 64);
        zero_kernel<<<z_grid, 256>>>((float4*)sout, NN * DD / 4);
        edge_kernel<<<e_grid, 256, WE_SMEM>>>(
            ab, sout, src, dst,
            Wh + (size_t)t * 64 * 64, b_h + (size_t)t * 64,
            Wout + (size_t)t * 64 * DD, b_out + (size_t)t * DD,
            b_in + (size_t)t * 64);
        sin = sout;
    }

    zero_kernel<<<8, 256>>>((float4*)mol, NMOL * DD / 4);
    pool_kernel<<<592, 256>>>(sin, molid, mol);
    mlp_kernel<<<NMOL, 64>>>(mol, fc1_w, fc1_b, fc2_w, fc2_b, out_w, out_b, out);
}